// round 12
// baseline (speedup 1.0000x reference)
#include <cuda_runtime.h>
#include <cuda_fp16.h>
#include <cstdint>

// =====================================================================
// QuantLinear W8A8 — fp16 legacy-HMMA GEMM (mma.sync m16n8k16), v6.
//   A = (Xq - zp[m]) exact in fp16; B = Wq exact in fp16
//   acc = A @ B^T (fp32), Y = acc * sa[m]*sw[n] + bias[n]
// v6: 256 threads / 8 warps (warp tile 64x32) to double warps/SMSP and
// drop regs off the 255 ceiling; keeps BK=64, XOR-8 swizzle, fragment
// double-buffer, cross-barrier ks=0 prefetch, 3-stage cp.async.
// =====================================================================

static constexpr int M_MAX = 8192;
static constexpr int N_MAX = 4096;
static constexpr int K_MAX = 4096;

__device__ __half g_xh[(size_t)M_MAX * K_MAX];   // Xq - zp
__device__ __half g_wh[(size_t)N_MAX * K_MAX];   // Wq
__device__ float  g_ascale[M_MAX];
__device__ float  g_wscale[N_MAX];

// ======================= PTX helpers =======================

__device__ __forceinline__ uint32_t smem_to_u32(const void* p) {
    uint32_t a;
    asm("{ .reg .u64 t; cvta.to.shared.u64 t, %1; cvt.u32.u64 %0, t; }"
        : "=r"(a) : "l"(p));
    return a;
}

__device__ __forceinline__ void cp_async16(uint32_t smem_addr, const void* gptr) {
    asm volatile("cp.async.cg.shared.global [%0], [%1], 16;\n"
                 :: "r"(smem_addr), "l"(gptr) : "memory");
}

#define CP_ASYNC_COMMIT() asm volatile("cp.async.commit_group;\n" ::: "memory")
#define CP_ASYNC_WAIT(n)  asm volatile("cp.async.wait_group %0;\n" :: "n"(n) : "memory")

__device__ __forceinline__ void ldmatrix_x4(uint32_t& r0, uint32_t& r1,
                                            uint32_t& r2, uint32_t& r3,
                                            uint32_t addr) {
    asm volatile("ldmatrix.sync.aligned.m8n8.x4.shared.b16 {%0,%1,%2,%3}, [%4];"
                 : "=r"(r0), "=r"(r1), "=r"(r2), "=r"(r3) : "r"(addr));
}

__device__ __forceinline__ void hmma16816(float& c0, float& c1, float& c2, float& c3,
                                          uint32_t a0, uint32_t a1, uint32_t a2, uint32_t a3,
                                          uint32_t b0, uint32_t b1) {
    asm volatile(
        "mma.sync.aligned.m16n8k16.row.col.f32.f16.f16.f32 "
        "{%0,%1,%2,%3}, {%4,%5,%6,%7}, {%8,%9}, {%0,%1,%2,%3};"
        : "+f"(c0), "+f"(c1), "+f"(c2), "+f"(c3)
        : "r"(a0), "r"(a1), "r"(a2), "r"(a3), "r"(b0), "r"(b1));
}

// ======================= merged quantization kernel =======================

__global__ void __launch_bounds__(256)
quant_kernel(const float* __restrict__ w, const float* __restrict__ x,
             int Nrows, int K) {
    const bool is_w = (blockIdx.x < Nrows);
    const int r = is_w ? blockIdx.x : (blockIdx.x - Nrows);
    const float4* row = reinterpret_cast<const float4*>(
        (is_w ? w : x) + (size_t)r * K);
    const int nv = K >> 2;
    const bool fast = (nv == 4 * 256);

    float4 v[4];
    float vmin = 3.0e38f, vmax = -3.0e38f;
    if (fast) {
        #pragma unroll
        for (int j = 0; j < 4; j++) v[j] = row[threadIdx.x + j * 256];
        #pragma unroll
        for (int j = 0; j < 4; j++) {
            vmin = fminf(vmin, fminf(fminf(v[j].x, v[j].y), fminf(v[j].z, v[j].w)));
            vmax = fmaxf(vmax, fmaxf(fmaxf(v[j].x, v[j].y), fmaxf(v[j].z, v[j].w)));
        }
    } else {
        for (int i = threadIdx.x; i < nv; i += blockDim.x) {
            float4 t = row[i];
            vmin = fminf(vmin, fminf(fminf(t.x, t.y), fminf(t.z, t.w)));
            vmax = fmaxf(vmax, fmaxf(fmaxf(t.x, t.y), fmaxf(t.z, t.w)));
        }
    }
    #pragma unroll
    for (int o = 16; o; o >>= 1) {
        vmin = fminf(vmin, __shfl_xor_sync(0xFFFFFFFF, vmin, o));
        vmax = fmaxf(vmax, __shfl_xor_sync(0xFFFFFFFF, vmax, o));
    }
    __shared__ float s_min[8], s_max[8];
    __shared__ float s_inv, s_zp;
    const int wid = threadIdx.x >> 5;
    if ((threadIdx.x & 31) == 0) { s_min[wid] = vmin; s_max[wid] = vmax; }
    __syncthreads();
    if (threadIdx.x == 0) {
        float mn = s_min[0], mx = s_max[0];
        #pragma unroll
        for (int i = 1; i < 8; i++) { mn = fminf(mn, s_min[i]); mx = fmaxf(mx, s_max[i]); }
        if (is_w) {
            float a = fmaxf(fabsf(mn), fabsf(mx));
            float sc = (a > 0.0f) ? __fdiv_rn(a, 127.0f) : 1.0f;
            g_wscale[r] = sc;
            s_inv = __fdiv_rn(1.0f, sc);
            s_zp = 0.0f;
        } else {
            float rng = mx - mn;
            float sc = (rng > 0.0f) ? __fdiv_rn(rng, 255.0f) : 1.0f;
            float zp = rintf(__fdiv_rn(-mn, sc));
            g_ascale[r] = sc;
            s_inv = __fdiv_rn(1.0f, sc);
            s_zp = zp;
        }
    }
    __syncthreads();
    const float inv = s_inv, zp = s_zp;

    __half2* dst = reinterpret_cast<__half2*>(
        (is_w ? g_wh : g_xh) + (size_t)r * K);

    if (is_w) {
        if (fast) {
            #pragma unroll
            for (int j = 0; j < 4; j++) {
                const int i = threadIdx.x + j * 256;
                float q0 = fminf(fmaxf(rintf(v[j].x * inv), -127.0f), 127.0f);
                float q1 = fminf(fmaxf(rintf(v[j].y * inv), -127.0f), 127.0f);
                float q2 = fminf(fmaxf(rintf(v[j].z * inv), -127.0f), 127.0f);
                float q3 = fminf(fmaxf(rintf(v[j].w * inv), -127.0f), 127.0f);
                dst[2 * i]     = __floats2half2_rn(q0, q1);
                dst[2 * i + 1] = __floats2half2_rn(q2, q3);
            }
        } else {
            for (int i = threadIdx.x; i < nv; i += blockDim.x) {
                float4 t = row[i];
                float q0 = fminf(fmaxf(rintf(t.x * inv), -127.0f), 127.0f);
                float q1 = fminf(fmaxf(rintf(t.y * inv), -127.0f), 127.0f);
                float q2 = fminf(fmaxf(rintf(t.z * inv), -127.0f), 127.0f);
                float q3 = fminf(fmaxf(rintf(t.w * inv), -127.0f), 127.0f);
                dst[2 * i]     = __floats2half2_rn(q0, q1);
                dst[2 * i + 1] = __floats2half2_rn(q2, q3);
            }
        }
    } else {
        if (fast) {
            #pragma unroll
            for (int j = 0; j < 4; j++) {
                const int i = threadIdx.x + j * 256;
                float q0 = fminf(fmaxf(rintf(v[j].x * inv) + zp, 0.0f), 255.0f) - zp;
                float q1 = fminf(fmaxf(rintf(v[j].y * inv) + zp, 0.0f), 255.0f) - zp;
                float q2 = fminf(fmaxf(rintf(v[j].z * inv) + zp, 0.0f), 255.0f) - zp;
                float q3 = fminf(fmaxf(rintf(v[j].w * inv) + zp, 0.0f), 255.0f) - zp;
                dst[2 * i]     = __floats2half2_rn(q0, q1);
                dst[2 * i + 1] = __floats2half2_rn(q2, q3);
            }
        } else {
            for (int i = threadIdx.x; i < nv; i += blockDim.x) {
                float4 t = row[i];
                float q0 = fminf(fmaxf(rintf(t.x * inv) + zp, 0.0f), 255.0f) - zp;
                float q1 = fminf(fmaxf(rintf(t.y * inv) + zp, 0.0f), 255.0f) - zp;
                float q2 = fminf(fmaxf(rintf(t.z * inv) + zp, 0.0f), 255.0f) - zp;
                float q3 = fminf(fmaxf(rintf(t.w * inv) + zp, 0.0f), 255.0f) - zp;
                dst[2 * i]     = __floats2half2_rn(q0, q1);
                dst[2 * i + 1] = __floats2half2_rn(q2, q3);
            }
        }
    }
}

// ======================= fp16 GEMM kernel v6 =======================
// CTA 128x128, 256 threads = 8 warps (2x4), warp tile 64x32.
// BK=64 halfs = 128B rows, XOR-8 swizzle, 3 stages, 96KB smem.

static constexpr int STAGES = 3;
static constexpr int STAGE_BYTES = 32768;                 // A 16K + B 16K
static constexpr int GEMM_SMEM = STAGES * STAGE_BYTES;    // 96KB

__global__ void __launch_bounds__(256)
gemm_kernel(float* __restrict__ out, const float* __restrict__ bias,
            int M, int N, int K) {
    extern __shared__ __align__(1024) uint8_t smem[];
    const uint32_t smem_u32 = smem_to_u32(smem);

    const int tid  = threadIdx.x;
    const int lane = tid & 31;
    const int wid  = tid >> 5;
    const int m0 = blockIdx.y * 128;
    const int n0 = blockIdx.x * 128;
    const int warp_m = (wid >> 2) * 64;   // 0 or 64
    const int warp_n = (wid & 3) * 32;    // 0,32,64,96

    const size_t Kb = (size_t)K * 2;
    const int KT = K >> 6;                // 64-half (128B) chunks

    const uint8_t* gA = reinterpret_cast<const uint8_t*>(g_xh) + (size_t)m0 * Kb;
    const uint8_t* gB = reinterpret_cast<const uint8_t*>(g_wh) + (size_t)n0 * Kb;

    // per stage: A 1024 chunks + B 1024 chunks; 256 threads x 4 j-iters
    auto issue_part = [&](int kt, int s, int part) {
        if (kt < KT) {
            uint32_t sa = smem_u32 + s * STAGE_BYTES;
            uint32_t sb = sa + 16384;
            const uint8_t* ga = gA + (size_t)kt * 128;
            const uint8_t* gb = gB + (size_t)kt * 128;
            int idx = tid + part * 256;       // 0..1023
            int row = idx >> 3;
            int c   = idx & 7;
            int cs  = c ^ (row & 7);
            cp_async16(sa + row * 128 + (cs << 4), ga + (size_t)row * Kb + c * 16);
            cp_async16(sb + row * 128 + (cs << 4), gb + (size_t)row * Kb + c * 16);
        }
        if (part == 3) CP_ASYNC_COMMIT();
    };

    auto issue_full = [&](int kt, int s) {
        #pragma unroll
        for (int p = 0; p < 4; p++) issue_part(kt, s, p);
    };

    const int a_row = lane & 15;
    const int a_cs  = lane >> 4;
    const int a_swz = a_row & 7;
    const int b_row = (lane & 7) + ((lane >> 4) << 3);
    const int b_cs  = (lane >> 3) & 1;
    const int b_swz = b_row & 7;

    float acc[4][4][4];
    #pragma unroll
    for (int i = 0; i < 4; i++)
        #pragma unroll
        for (int j = 0; j < 4; j++)
            #pragma unroll
            for (int r = 0; r < 4; r++) acc[i][j][r] = 0.0f;

    uint32_t af[2][4][4];
    uint32_t bf[2][2][4];

    auto load_frags = [&](uint32_t sa, uint32_t sb, int ks, int buf) {
        #pragma unroll
        for (int mf = 0; mf < 4; mf++) {
            uint32_t addr = sa + (warp_m + mf * 16 + a_row) * 128
                          + (((2 * ks + a_cs) ^ a_swz) << 4);
            ldmatrix_x4(af[buf][mf][0], af[buf][mf][1],
                        af[buf][mf][2], af[buf][mf][3], addr);
        }
        #pragma unroll
        for (int p = 0; p < 2; p++) {
            uint32_t addr = sb + (warp_n + p * 16 + b_row) * 128
                          + (((2 * ks + b_cs) ^ b_swz) << 4);
            ldmatrix_x4(bf[buf][p][0], bf[buf][p][1],
                        bf[buf][p][2], bf[buf][p][3], addr);
        }
    };

    auto compute = [&](int buf) {
        #pragma unroll
        for (int mf = 0; mf < 4; mf++) {
            #pragma unroll
            for (int nf = 0; nf < 4; nf++) {
                const int p = nf >> 1, h = (nf & 1) << 1;
                hmma16816(acc[mf][nf][0], acc[mf][nf][1],
                          acc[mf][nf][2], acc[mf][nf][3],
                          af[buf][mf][0], af[buf][mf][1],
                          af[buf][mf][2], af[buf][mf][3],
                          bf[buf][p][h], bf[buf][p][h + 1]);
            }
        }
    };

    // prologue
    issue_full(0, 0);
    issue_full(1, 1);
    CP_ASYNC_WAIT(1);
    __syncthreads();
    load_frags(smem_u32, smem_u32 + 16384, 0, 0);

    for (int kt = 0; kt < KT; kt++) {
        const int s = kt % STAGES;
        const uint32_t sa = smem_u32 + s * STAGE_BYTES;
        const uint32_t sb = sa + 16384;
        const int kt_next = kt + STAGES - 1;
        const int s_next = kt_next % STAGES;
        const int s1 = (kt + 1) % STAGES;
        const uint32_t sa1 = smem_u32 + s1 * STAGE_BYTES;
        const uint32_t sb1 = sa1 + 16384;

        #pragma unroll
        for (int ks = 0; ks < 4; ks++) {
            issue_part(kt_next, s_next, ks);       // commit at ks==3
            if (ks < 3) {
                load_frags(sa, sb, ks + 1, (ks + 1) & 1);
            } else {
                CP_ASYNC_WAIT(1);                  // stage kt+1 data landed
                __syncthreads();                   // all reads of stage kt done
                load_frags(sa1, sb1, 0, 0);        // prefetch next chunk ks=0
            }
            compute(ks & 1);
        }
    }

    // ================= epilogue =================
    #pragma unroll
    for (int mf = 0; mf < 4; mf++) {
        const int gr0 = m0 + warp_m + mf * 16 + (lane >> 2);
        const int gr1 = gr0 + 8;
        const float sa0 = g_ascale[gr0];
        const float sa1 = g_ascale[gr1];
        #pragma unroll
        for (int nf = 0; nf < 4; nf++) {
            const int gc = n0 + warp_n + nf * 8 + 2 * (lane & 3);
            const float sw0 = g_wscale[gc], sw1 = g_wscale[gc + 1];
            const float bb0 = bias[gc],     bb1 = bias[gc + 1];
            float2 v0, v1;
            v0.x = acc[mf][nf][0] * (sa0 * sw0) + bb0;
            v0.y = acc[mf][nf][1] * (sa0 * sw1) + bb1;
            v1.x = acc[mf][nf][2] * (sa1 * sw0) + bb0;
            v1.y = acc[mf][nf][3] * (sa1 * sw1) + bb1;
            *reinterpret_cast<float2*>(out + (size_t)gr0 * N + gc) = v0;
            *reinterpret_cast<float2*>(out + (size_t)gr1 * N + gc) = v1;
        }
    }
}

// ======================= launch =======================

extern "C" void kernel_launch(void* const* d_in, const int* in_sizes, int n_in,
                              void* d_out, int out_size) {
    const float* x    = (const float*)d_in[0];
    const float* w    = (const float*)d_in[1];
    const float* bias = (const float*)d_in[2];
    float* out        = (float*)d_out;

    const int N = in_sizes[2];          // 4096
    const int K = in_sizes[1] / N;      // 4096
    const int M = in_sizes[0] / K;      // 8192

    cudaFuncSetAttribute(gemm_kernel,
                         cudaFuncAttributeMaxDynamicSharedMemorySize, GEMM_SMEM);

    quant_kernel<<<N + M, 256>>>(w, x, N, K);

    dim3 grid(N / 128, M / 128);
    gemm_kernel<<<grid, 256, GEMM_SMEM>>>(out, bias, M, N, K);
}

// round 13
// speedup vs baseline: 1.0545x; 1.0545x over previous
#include <cuda_runtime.h>
#include <cuda_fp16.h>
#include <cstdint>

// =====================================================================
// QuantLinear W8A8 — fp16 legacy-HMMA GEMM (mma.sync m16n8k16), v7.
//   A = (Xq - zp[m]) exact in fp16; B = Wq exact in fp16
//   acc = A @ B^T (fp32), Y = acc * sa[m]*sw[n] + bias[n]
// v7 = v6 + __launch_bounds__(256, 2): cap regs at 128 so TWO CTAs fit
// the 64K-reg SM file -> 16 warps/SM (4/SMSP) with per-CTA barriers.
// CTA 128x128, 8 warps (64x32), BK=64, XOR-8 swizzle, frag double-
// buffer, cross-barrier ks=0 prefetch, 3-stage cp.async, 96KB smem.
// =====================================================================

static constexpr int M_MAX = 8192;
static constexpr int N_MAX = 4096;
static constexpr int K_MAX = 4096;

__device__ __half g_xh[(size_t)M_MAX * K_MAX];   // Xq - zp
__device__ __half g_wh[(size_t)N_MAX * K_MAX];   // Wq
__device__ float  g_ascale[M_MAX];
__device__ float  g_wscale[N_MAX];

// ======================= PTX helpers =======================

__device__ __forceinline__ uint32_t smem_to_u32(const void* p) {
    uint32_t a;
    asm("{ .reg .u64 t; cvta.to.shared.u64 t, %1; cvt.u32.u64 %0, t; }"
        : "=r"(a) : "l"(p));
    return a;
}

__device__ __forceinline__ void cp_async16(uint32_t smem_addr, const void* gptr) {
    asm volatile("cp.async.cg.shared.global [%0], [%1], 16;\n"
                 :: "r"(smem_addr), "l"(gptr) : "memory");
}

#define CP_ASYNC_COMMIT() asm volatile("cp.async.commit_group;\n" ::: "memory")
#define CP_ASYNC_WAIT(n)  asm volatile("cp.async.wait_group %0;\n" :: "n"(n) : "memory")

__device__ __forceinline__ void ldmatrix_x4(uint32_t& r0, uint32_t& r1,
                                            uint32_t& r2, uint32_t& r3,
                                            uint32_t addr) {
    asm volatile("ldmatrix.sync.aligned.m8n8.x4.shared.b16 {%0,%1,%2,%3}, [%4];"
                 : "=r"(r0), "=r"(r1), "=r"(r2), "=r"(r3) : "r"(addr));
}

__device__ __forceinline__ void hmma16816(float& c0, float& c1, float& c2, float& c3,
                                          uint32_t a0, uint32_t a1, uint32_t a2, uint32_t a3,
                                          uint32_t b0, uint32_t b1) {
    asm volatile(
        "mma.sync.aligned.m16n8k16.row.col.f32.f16.f16.f32 "
        "{%0,%1,%2,%3}, {%4,%5,%6,%7}, {%8,%9}, {%0,%1,%2,%3};"
        : "+f"(c0), "+f"(c1), "+f"(c2), "+f"(c3)
        : "r"(a0), "r"(a1), "r"(a2), "r"(a3), "r"(b0), "r"(b1));
}

// ======================= merged quantization kernel =======================

__global__ void __launch_bounds__(256)
quant_kernel(const float* __restrict__ w, const float* __restrict__ x,
             int Nrows, int K) {
    const bool is_w = (blockIdx.x < Nrows);
    const int r = is_w ? blockIdx.x : (blockIdx.x - Nrows);
    const float4* row = reinterpret_cast<const float4*>(
        (is_w ? w : x) + (size_t)r * K);
    const int nv = K >> 2;
    const bool fast = (nv == 4 * 256);

    float4 v[4];
    float vmin = 3.0e38f, vmax = -3.0e38f;
    if (fast) {
        #pragma unroll
        for (int j = 0; j < 4; j++) v[j] = row[threadIdx.x + j * 256];
        #pragma unroll
        for (int j = 0; j < 4; j++) {
            vmin = fminf(vmin, fminf(fminf(v[j].x, v[j].y), fminf(v[j].z, v[j].w)));
            vmax = fmaxf(vmax, fmaxf(fmaxf(v[j].x, v[j].y), fmaxf(v[j].z, v[j].w)));
        }
    } else {
        for (int i = threadIdx.x; i < nv; i += blockDim.x) {
            float4 t = row[i];
            vmin = fminf(vmin, fminf(fminf(t.x, t.y), fminf(t.z, t.w)));
            vmax = fmaxf(vmax, fmaxf(fmaxf(t.x, t.y), fmaxf(t.z, t.w)));
        }
    }
    #pragma unroll
    for (int o = 16; o; o >>= 1) {
        vmin = fminf(vmin, __shfl_xor_sync(0xFFFFFFFF, vmin, o));
        vmax = fmaxf(vmax, __shfl_xor_sync(0xFFFFFFFF, vmax, o));
    }
    __shared__ float s_min[8], s_max[8];
    __shared__ float s_inv, s_zp;
    const int wid = threadIdx.x >> 5;
    if ((threadIdx.x & 31) == 0) { s_min[wid] = vmin; s_max[wid] = vmax; }
    __syncthreads();
    if (threadIdx.x == 0) {
        float mn = s_min[0], mx = s_max[0];
        #pragma unroll
        for (int i = 1; i < 8; i++) { mn = fminf(mn, s_min[i]); mx = fmaxf(mx, s_max[i]); }
        if (is_w) {
            float a = fmaxf(fabsf(mn), fabsf(mx));
            float sc = (a > 0.0f) ? __fdiv_rn(a, 127.0f) : 1.0f;
            g_wscale[r] = sc;
            s_inv = __fdiv_rn(1.0f, sc);
            s_zp = 0.0f;
        } else {
            float rng = mx - mn;
            float sc = (rng > 0.0f) ? __fdiv_rn(rng, 255.0f) : 1.0f;
            float zp = rintf(__fdiv_rn(-mn, sc));
            g_ascale[r] = sc;
            s_inv = __fdiv_rn(1.0f, sc);
            s_zp = zp;
        }
    }
    __syncthreads();
    const float inv = s_inv, zp = s_zp;

    __half2* dst = reinterpret_cast<__half2*>(
        (is_w ? g_wh : g_xh) + (size_t)r * K);

    if (is_w) {
        if (fast) {
            #pragma unroll
            for (int j = 0; j < 4; j++) {
                const int i = threadIdx.x + j * 256;
                float q0 = fminf(fmaxf(rintf(v[j].x * inv), -127.0f), 127.0f);
                float q1 = fminf(fmaxf(rintf(v[j].y * inv), -127.0f), 127.0f);
                float q2 = fminf(fmaxf(rintf(v[j].z * inv), -127.0f), 127.0f);
                float q3 = fminf(fmaxf(rintf(v[j].w * inv), -127.0f), 127.0f);
                dst[2 * i]     = __floats2half2_rn(q0, q1);
                dst[2 * i + 1] = __floats2half2_rn(q2, q3);
            }
        } else {
            for (int i = threadIdx.x; i < nv; i += blockDim.x) {
                float4 t = row[i];
                float q0 = fminf(fmaxf(rintf(t.x * inv), -127.0f), 127.0f);
                float q1 = fminf(fmaxf(rintf(t.y * inv), -127.0f), 127.0f);
                float q2 = fminf(fmaxf(rintf(t.z * inv), -127.0f), 127.0f);
                float q3 = fminf(fmaxf(rintf(t.w * inv), -127.0f), 127.0f);
                dst[2 * i]     = __floats2half2_rn(q0, q1);
                dst[2 * i + 1] = __floats2half2_rn(q2, q3);
            }
        }
    } else {
        if (fast) {
            #pragma unroll
            for (int j = 0; j < 4; j++) {
                const int i = threadIdx.x + j * 256;
                float q0 = fminf(fmaxf(rintf(v[j].x * inv) + zp, 0.0f), 255.0f) - zp;
                float q1 = fminf(fmaxf(rintf(v[j].y * inv) + zp, 0.0f), 255.0f) - zp;
                float q2 = fminf(fmaxf(rintf(v[j].z * inv) + zp, 0.0f), 255.0f) - zp;
                float q3 = fminf(fmaxf(rintf(v[j].w * inv) + zp, 0.0f), 255.0f) - zp;
                dst[2 * i]     = __floats2half2_rn(q0, q1);
                dst[2 * i + 1] = __floats2half2_rn(q2, q3);
            }
        } else {
            for (int i = threadIdx.x; i < nv; i += blockDim.x) {
                float4 t = row[i];
                float q0 = fminf(fmaxf(rintf(t.x * inv) + zp, 0.0f), 255.0f) - zp;
                float q1 = fminf(fmaxf(rintf(t.y * inv) + zp, 0.0f), 255.0f) - zp;
                float q2 = fminf(fmaxf(rintf(t.z * inv) + zp, 0.0f), 255.0f) - zp;
                float q3 = fminf(fmaxf(rintf(t.w * inv) + zp, 0.0f), 255.0f) - zp;
                dst[2 * i]     = __floats2half2_rn(q0, q1);
                dst[2 * i + 1] = __floats2half2_rn(q2, q3);
            }
        }
    }
}

// ======================= fp16 GEMM kernel v7 =======================
// CTA 128x128, 256 threads = 8 warps (2x4), warp tile 64x32.
// __launch_bounds__(256, 2): cap 128 regs -> 2 CTAs/SM (regfile-fit).

static constexpr int STAGES = 3;
static constexpr int STAGE_BYTES = 32768;                 // A 16K + B 16K
static constexpr int GEMM_SMEM = STAGES * STAGE_BYTES;    // 96KB

__global__ void __launch_bounds__(256, 2)
gemm_kernel(float* __restrict__ out, const float* __restrict__ bias,
            int M, int N, int K) {
    extern __shared__ __align__(1024) uint8_t smem[];
    const uint32_t smem_u32 = smem_to_u32(smem);

    const int tid  = threadIdx.x;
    const int lane = tid & 31;
    const int wid  = tid >> 5;
    const int m0 = blockIdx.y * 128;
    const int n0 = blockIdx.x * 128;
    const int warp_m = (wid >> 2) * 64;   // 0 or 64
    const int warp_n = (wid & 3) * 32;    // 0,32,64,96

    const size_t Kb = (size_t)K * 2;
    const int KT = K >> 6;                // 64-half (128B) chunks

    const uint8_t* gA = reinterpret_cast<const uint8_t*>(g_xh) + (size_t)m0 * Kb;
    const uint8_t* gB = reinterpret_cast<const uint8_t*>(g_wh) + (size_t)n0 * Kb;

    auto issue_part = [&](int kt, int s, int part) {
        if (kt < KT) {
            uint32_t sa = smem_u32 + s * STAGE_BYTES;
            uint32_t sb = sa + 16384;
            const uint8_t* ga = gA + (size_t)kt * 128;
            const uint8_t* gb = gB + (size_t)kt * 128;
            int idx = tid + part * 256;       // 0..1023
            int row = idx >> 3;
            int c   = idx & 7;
            int cs  = c ^ (row & 7);
            cp_async16(sa + row * 128 + (cs << 4), ga + (size_t)row * Kb + c * 16);
            cp_async16(sb + row * 128 + (cs << 4), gb + (size_t)row * Kb + c * 16);
        }
        if (part == 3) CP_ASYNC_COMMIT();
    };

    auto issue_full = [&](int kt, int s) {
        #pragma unroll
        for (int p = 0; p < 4; p++) issue_part(kt, s, p);
    };

    const int a_row = lane & 15;
    const int a_cs  = lane >> 4;
    const int a_swz = a_row & 7;
    const int b_row = (lane & 7) + ((lane >> 4) << 3);
    const int b_cs  = (lane >> 3) & 1;
    const int b_swz = b_row & 7;

    float acc[4][4][4];
    #pragma unroll
    for (int i = 0; i < 4; i++)
        #pragma unroll
        for (int j = 0; j < 4; j++)
            #pragma unroll
            for (int r = 0; r < 4; r++) acc[i][j][r] = 0.0f;

    uint32_t af[2][4][4];
    uint32_t bf[2][2][4];

    auto load_frags = [&](uint32_t sa, uint32_t sb, int ks, int buf) {
        #pragma unroll
        for (int mf = 0; mf < 4; mf++) {
            uint32_t addr = sa + (warp_m + mf * 16 + a_row) * 128
                          + (((2 * ks + a_cs) ^ a_swz) << 4);
            ldmatrix_x4(af[buf][mf][0], af[buf][mf][1],
                        af[buf][mf][2], af[buf][mf][3], addr);
        }
        #pragma unroll
        for (int p = 0; p < 2; p++) {
            uint32_t addr = sb + (warp_n + p * 16 + b_row) * 128
                          + (((2 * ks + b_cs) ^ b_swz) << 4);
            ldmatrix_x4(bf[buf][p][0], bf[buf][p][1],
                        bf[buf][p][2], bf[buf][p][3], addr);
        }
    };

    auto compute = [&](int buf) {
        #pragma unroll
        for (int mf = 0; mf < 4; mf++) {
            #pragma unroll
            for (int nf = 0; nf < 4; nf++) {
                const int p = nf >> 1, h = (nf & 1) << 1;
                hmma16816(acc[mf][nf][0], acc[mf][nf][1],
                          acc[mf][nf][2], acc[mf][nf][3],
                          af[buf][mf][0], af[buf][mf][1],
                          af[buf][mf][2], af[buf][mf][3],
                          bf[buf][p][h], bf[buf][p][h + 1]);
            }
        }
    };

    // prologue
    issue_full(0, 0);
    issue_full(1, 1);
    CP_ASYNC_WAIT(1);
    __syncthreads();
    load_frags(smem_u32, smem_u32 + 16384, 0, 0);

    for (int kt = 0; kt < KT; kt++) {
        const int s = kt % STAGES;
        const uint32_t sa = smem_u32 + s * STAGE_BYTES;
        const uint32_t sb = sa + 16384;
        const int kt_next = kt + STAGES - 1;
        const int s_next = kt_next % STAGES;
        const int s1 = (kt + 1) % STAGES;
        const uint32_t sa1 = smem_u32 + s1 * STAGE_BYTES;
        const uint32_t sb1 = sa1 + 16384;

        #pragma unroll
        for (int ks = 0; ks < 4; ks++) {
            issue_part(kt_next, s_next, ks);       // commit at ks==3
            if (ks < 3) {
                load_frags(sa, sb, ks + 1, (ks + 1) & 1);
            } else {
                CP_ASYNC_WAIT(1);                  // stage kt+1 data landed
                __syncthreads();                   // all reads of stage kt done
                load_frags(sa1, sb1, 0, 0);        // prefetch next chunk ks=0
            }
            compute(ks & 1);
        }
    }

    // ================= epilogue =================
    #pragma unroll
    for (int mf = 0; mf < 4; mf++) {
        const int gr0 = m0 + warp_m + mf * 16 + (lane >> 2);
        const int gr1 = gr0 + 8;
        const float sa0 = g_ascale[gr0];
        const float sa1 = g_ascale[gr1];
        #pragma unroll
        for (int nf = 0; nf < 4; nf++) {
            const int gc = n0 + warp_n + nf * 8 + 2 * (lane & 3);
            const float sw0 = g_wscale[gc], sw1 = g_wscale[gc + 1];
            const float bb0 = bias[gc],     bb1 = bias[gc + 1];
            float2 v0, v1;
            v0.x = acc[mf][nf][0] * (sa0 * sw0) + bb0;
            v0.y = acc[mf][nf][1] * (sa0 * sw1) + bb1;
            v1.x = acc[mf][nf][2] * (sa1 * sw0) + bb0;
            v1.y = acc[mf][nf][3] * (sa1 * sw1) + bb1;
            *reinterpret_cast<float2*>(out + (size_t)gr0 * N + gc) = v0;
            *reinterpret_cast<float2*>(out + (size_t)gr1 * N + gc) = v1;
        }
    }
}

// ======================= launch =======================

extern "C" void kernel_launch(void* const* d_in, const int* in_sizes, int n_in,
                              void* d_out, int out_size) {
    const float* x    = (const float*)d_in[0];
    const float* w    = (const float*)d_in[1];
    const float* bias = (const float*)d_in[2];
    float* out        = (float*)d_out;

    const int N = in_sizes[2];          // 4096
    const int K = in_sizes[1] / N;      // 4096
    const int M = in_sizes[0] / K;      // 8192

    cudaFuncSetAttribute(gemm_kernel,
                         cudaFuncAttributeMaxDynamicSharedMemorySize, GEMM_SMEM);

    quant_kernel<<<N + M, 256>>>(w, x, N, K);

    dim3 grid(N / 128, M / 128);
    gemm_kernel<<<grid, 256, GEMM_SMEM>>>(out, bias, M, N, K);
}

// round 14
// speedup vs baseline: 1.2251x; 1.1617x over previous
#include <cuda_runtime.h>
#include <cuda_fp16.h>
#include <cstdint>

// =====================================================================
// QuantLinear W8A8 — fp16 legacy-HMMA GEMM (mma.sync m16n8k16), v8.
//   A = (Xq - zp[m]) exact in fp16; B = Wq exact in fp16
//   acc = A @ B^T (fp32), Y = acc * sa[m]*sw[n] + bias[n]
// v8 = R11 config (CTA 128x128, 4 warps of 64x64, BK=64, XOR-8 swizzle,
// frag double-buffer, 3-stage cp.async, 96KB) made PERSISTENT: 296 CTAs,
// ~7 tiles each, cp.async + fragment pipeline streaming ACROSS tile
// boundaries so epilogue/prologue latency is hidden behind the next
// tile's loads.
// =====================================================================

static constexpr int M_MAX = 8192;
static constexpr int N_MAX = 4096;
static constexpr int K_MAX = 4096;

__device__ __half g_xh[(size_t)M_MAX * K_MAX];   // Xq - zp
__device__ __half g_wh[(size_t)N_MAX * K_MAX];   // Wq
__device__ float  g_ascale[M_MAX];
__device__ float  g_wscale[N_MAX];

// ======================= PTX helpers =======================

__device__ __forceinline__ uint32_t smem_to_u32(const void* p) {
    uint32_t a;
    asm("{ .reg .u64 t; cvta.to.shared.u64 t, %1; cvt.u32.u64 %0, t; }"
        : "=r"(a) : "l"(p));
    return a;
}

__device__ __forceinline__ void cp_async16(uint32_t smem_addr, const void* gptr) {
    asm volatile("cp.async.cg.shared.global [%0], [%1], 16;\n"
                 :: "r"(smem_addr), "l"(gptr) : "memory");
}

#define CP_ASYNC_COMMIT() asm volatile("cp.async.commit_group;\n" ::: "memory")
#define CP_ASYNC_WAIT(n)  asm volatile("cp.async.wait_group %0;\n" :: "n"(n) : "memory")

__device__ __forceinline__ void ldmatrix_x4(uint32_t& r0, uint32_t& r1,
                                            uint32_t& r2, uint32_t& r3,
                                            uint32_t addr) {
    asm volatile("ldmatrix.sync.aligned.m8n8.x4.shared.b16 {%0,%1,%2,%3}, [%4];"
                 : "=r"(r0), "=r"(r1), "=r"(r2), "=r"(r3) : "r"(addr));
}

__device__ __forceinline__ void hmma16816(float& c0, float& c1, float& c2, float& c3,
                                          uint32_t a0, uint32_t a1, uint32_t a2, uint32_t a3,
                                          uint32_t b0, uint32_t b1) {
    asm volatile(
        "mma.sync.aligned.m16n8k16.row.col.f32.f16.f16.f32 "
        "{%0,%1,%2,%3}, {%4,%5,%6,%7}, {%8,%9}, {%0,%1,%2,%3};"
        : "+f"(c0), "+f"(c1), "+f"(c2), "+f"(c3)
        : "r"(a0), "r"(a1), "r"(a2), "r"(a3), "r"(b0), "r"(b1));
}

// ======================= merged quantization kernel =======================

__global__ void __launch_bounds__(256)
quant_kernel(const float* __restrict__ w, const float* __restrict__ x,
             int Nrows, int K) {
    const bool is_w = (blockIdx.x < Nrows);
    const int r = is_w ? blockIdx.x : (blockIdx.x - Nrows);
    const float4* row = reinterpret_cast<const float4*>(
        (is_w ? w : x) + (size_t)r * K);
    const int nv = K >> 2;
    const bool fast = (nv == 4 * 256);

    float4 v[4];
    float vmin = 3.0e38f, vmax = -3.0e38f;
    if (fast) {
        #pragma unroll
        for (int j = 0; j < 4; j++) v[j] = row[threadIdx.x + j * 256];
        #pragma unroll
        for (int j = 0; j < 4; j++) {
            vmin = fminf(vmin, fminf(fminf(v[j].x, v[j].y), fminf(v[j].z, v[j].w)));
            vmax = fmaxf(vmax, fmaxf(fmaxf(v[j].x, v[j].y), fmaxf(v[j].z, v[j].w)));
        }
    } else {
        for (int i = threadIdx.x; i < nv; i += blockDim.x) {
            float4 t = row[i];
            vmin = fminf(vmin, fminf(fminf(t.x, t.y), fminf(t.z, t.w)));
            vmax = fmaxf(vmax, fmaxf(fmaxf(t.x, t.y), fmaxf(t.z, t.w)));
        }
    }
    #pragma unroll
    for (int o = 16; o; o >>= 1) {
        vmin = fminf(vmin, __shfl_xor_sync(0xFFFFFFFF, vmin, o));
        vmax = fmaxf(vmax, __shfl_xor_sync(0xFFFFFFFF, vmax, o));
    }
    __shared__ float s_min[8], s_max[8];
    __shared__ float s_inv, s_zp;
    const int wid = threadIdx.x >> 5;
    if ((threadIdx.x & 31) == 0) { s_min[wid] = vmin; s_max[wid] = vmax; }
    __syncthreads();
    if (threadIdx.x == 0) {
        float mn = s_min[0], mx = s_max[0];
        #pragma unroll
        for (int i = 1; i < 8; i++) { mn = fminf(mn, s_min[i]); mx = fmaxf(mx, s_max[i]); }
        if (is_w) {
            float a = fmaxf(fabsf(mn), fabsf(mx));
            float sc = (a > 0.0f) ? __fdiv_rn(a, 127.0f) : 1.0f;
            g_wscale[r] = sc;
            s_inv = __fdiv_rn(1.0f, sc);
            s_zp = 0.0f;
        } else {
            float rng = mx - mn;
            float sc = (rng > 0.0f) ? __fdiv_rn(rng, 255.0f) : 1.0f;
            float zp = rintf(__fdiv_rn(-mn, sc));
            g_ascale[r] = sc;
            s_inv = __fdiv_rn(1.0f, sc);
            s_zp = zp;
        }
    }
    __syncthreads();
    const float inv = s_inv, zp = s_zp;

    __half2* dst = reinterpret_cast<__half2*>(
        (is_w ? g_wh : g_xh) + (size_t)r * K);

    if (is_w) {
        if (fast) {
            #pragma unroll
            for (int j = 0; j < 4; j++) {
                const int i = threadIdx.x + j * 256;
                float q0 = fminf(fmaxf(rintf(v[j].x * inv), -127.0f), 127.0f);
                float q1 = fminf(fmaxf(rintf(v[j].y * inv), -127.0f), 127.0f);
                float q2 = fminf(fmaxf(rintf(v[j].z * inv), -127.0f), 127.0f);
                float q3 = fminf(fmaxf(rintf(v[j].w * inv), -127.0f), 127.0f);
                dst[2 * i]     = __floats2half2_rn(q0, q1);
                dst[2 * i + 1] = __floats2half2_rn(q2, q3);
            }
        } else {
            for (int i = threadIdx.x; i < nv; i += blockDim.x) {
                float4 t = row[i];
                float q0 = fminf(fmaxf(rintf(t.x * inv), -127.0f), 127.0f);
                float q1 = fminf(fmaxf(rintf(t.y * inv), -127.0f), 127.0f);
                float q2 = fminf(fmaxf(rintf(t.z * inv), -127.0f), 127.0f);
                float q3 = fminf(fmaxf(rintf(t.w * inv), -127.0f), 127.0f);
                dst[2 * i]     = __floats2half2_rn(q0, q1);
                dst[2 * i + 1] = __floats2half2_rn(q2, q3);
            }
        }
    } else {
        if (fast) {
            #pragma unroll
            for (int j = 0; j < 4; j++) {
                const int i = threadIdx.x + j * 256;
                float q0 = fminf(fmaxf(rintf(v[j].x * inv) + zp, 0.0f), 255.0f) - zp;
                float q1 = fminf(fmaxf(rintf(v[j].y * inv) + zp, 0.0f), 255.0f) - zp;
                float q2 = fminf(fmaxf(rintf(v[j].z * inv) + zp, 0.0f), 255.0f) - zp;
                float q3 = fminf(fmaxf(rintf(v[j].w * inv) + zp, 0.0f), 255.0f) - zp;
                dst[2 * i]     = __floats2half2_rn(q0, q1);
                dst[2 * i + 1] = __floats2half2_rn(q2, q3);
            }
        } else {
            for (int i = threadIdx.x; i < nv; i += blockDim.x) {
                float4 t = row[i];
                float q0 = fminf(fmaxf(rintf(t.x * inv) + zp, 0.0f), 255.0f) - zp;
                float q1 = fminf(fmaxf(rintf(t.y * inv) + zp, 0.0f), 255.0f) - zp;
                float q2 = fminf(fmaxf(rintf(t.z * inv) + zp, 0.0f), 255.0f) - zp;
                float q3 = fminf(fmaxf(rintf(t.w * inv) + zp, 0.0f), 255.0f) - zp;
                dst[2 * i]     = __floats2half2_rn(q0, q1);
                dst[2 * i + 1] = __floats2half2_rn(q2, q3);
            }
        }
    }
}

// ======================= fp16 GEMM kernel v8 (persistent) =======================

static constexpr int STAGES = 3;
static constexpr int STAGE_BYTES = 32768;                 // A 16K + B 16K
static constexpr int GEMM_SMEM = STAGES * STAGE_BYTES;    // 96KB

__global__ void __launch_bounds__(128)
gemm_kernel(float* __restrict__ out, const float* __restrict__ bias,
            int M, int N, int K) {
    extern __shared__ __align__(1024) uint8_t smem[];
    const uint32_t smem_u32 = smem_to_u32(smem);

    const int tid  = threadIdx.x;
    const int lane = tid & 31;
    const int wid  = tid >> 5;
    const int warp_m = (wid >> 1) * 64;
    const int warp_n = (wid & 1) * 64;

    const size_t Kb = (size_t)K * 2;
    const int KT = K >> 6;                 // 128B chunks per tile
    const int NT = N >> 7;                 // tiles per row
    const int ntiles = (M >> 7) * NT;

    int tile = blockIdx.x;
    if (tile >= ntiles) return;
    int m0 = (tile / NT) << 7;
    int n0 = (tile % NT) << 7;
    int tile_nx = tile + gridDim.x;
    bool has_next = (tile_nx < ntiles);
    int m0n = 0, n0n = 0;
    if (has_next) { m0n = (tile_nx / NT) << 7; n0n = (tile_nx % NT) << 7; }

    const uint8_t* baseA = reinterpret_cast<const uint8_t*>(g_xh);
    const uint8_t* baseB = reinterpret_cast<const uint8_t*>(g_wh);

    // issue 2 of 8 copy iters for chunk (mx,nx,ktx) into stage s; commit at part 3
    auto issue_part = [&](int mx, int nx, int ktx, int s, int part, bool valid) {
        if (valid) {
            uint32_t sa = smem_u32 + s * STAGE_BYTES;
            uint32_t sb = sa + 16384;
            const uint8_t* ga = baseA + (size_t)mx * Kb + (size_t)ktx * 128;
            const uint8_t* gb = baseB + (size_t)nx * Kb + (size_t)ktx * 128;
            #pragma unroll
            for (int jj = 0; jj < 2; jj++) {
                int j = part * 2 + jj;
                int idx = tid + j * 128;
                int row = idx >> 3;
                int c   = idx & 7;
                int cs  = c ^ (row & 7);
                cp_async16(sa + row * 128 + (cs << 4), ga + (size_t)row * Kb + c * 16);
                cp_async16(sb + row * 128 + (cs << 4), gb + (size_t)row * Kb + c * 16);
            }
        }
        if (part == 3) CP_ASYNC_COMMIT();
    };

    const int a_row = lane & 15;
    const int a_cs  = lane >> 4;
    const int a_swz = a_row & 7;
    const int b_row = (lane & 7) + ((lane >> 4) << 3);
    const int b_cs  = (lane >> 3) & 1;
    const int b_swz = b_row & 7;

    float acc[4][8][4];
    #pragma unroll
    for (int i = 0; i < 4; i++)
        #pragma unroll
        for (int j = 0; j < 8; j++)
            #pragma unroll
            for (int r = 0; r < 4; r++) acc[i][j][r] = 0.0f;

    uint32_t af[2][4][4];
    uint32_t bf[2][4][4];

    auto load_frags = [&](uint32_t sa, uint32_t sb, int ks, int buf) {
        #pragma unroll
        for (int mf = 0; mf < 4; mf++) {
            uint32_t addr = sa + (warp_m + mf * 16 + a_row) * 128
                          + (((2 * ks + a_cs) ^ a_swz) << 4);
            ldmatrix_x4(af[buf][mf][0], af[buf][mf][1],
                        af[buf][mf][2], af[buf][mf][3], addr);
        }
        #pragma unroll
        for (int p = 0; p < 4; p++) {
            uint32_t addr = sb + (warp_n + p * 16 + b_row) * 128
                          + (((2 * ks + b_cs) ^ b_swz) << 4);
            ldmatrix_x4(bf[buf][p][0], bf[buf][p][1],
                        bf[buf][p][2], bf[buf][p][3], addr);
        }
    };

    auto compute = [&](int buf) {
        #pragma unroll
        for (int mf = 0; mf < 4; mf++) {
            #pragma unroll
            for (int nf = 0; nf < 8; nf++) {
                const int p = nf >> 1, h = (nf & 1) << 1;
                hmma16816(acc[mf][nf][0], acc[mf][nf][1],
                          acc[mf][nf][2], acc[mf][nf][3],
                          af[buf][mf][0], af[buf][mf][1],
                          af[buf][mf][2], af[buf][mf][3],
                          bf[buf][p][h], bf[buf][p][h + 1]);
            }
        }
    };

    // ---- prologue (once per CTA) ----
    #pragma unroll
    for (int p = 0; p < 4; p++) issue_part(m0, n0, 0, 0, p, true);
    #pragma unroll
    for (int p = 0; p < 4; p++) issue_part(m0, n0, 1, 1, p, true);
    CP_ASYNC_WAIT(1);
    __syncthreads();
    load_frags(smem_u32, smem_u32 + 16384, 0, 0);

    int s_cur = 0;
    while (true) {
        for (int kt = 0; kt < KT; kt++) {
            int ktL = kt + 2;
            int mL = m0, nL = n0;
            bool vL = true;
            if (ktL >= KT) {                 // load target crosses into next tile
                ktL -= KT; mL = m0n; nL = n0n; vL = has_next;
            }
            const int s_nf   = (s_cur + 1 < STAGES) ? s_cur + 1 : s_cur + 1 - STAGES;
            const int s_load = (s_cur + 2 < STAGES) ? s_cur + 2 : s_cur + 2 - STAGES;
            const uint32_t sa  = smem_u32 + s_cur * STAGE_BYTES;
            const uint32_t sb  = sa + 16384;
            const uint32_t sa1 = smem_u32 + s_nf * STAGE_BYTES;
            const uint32_t sb1 = sa1 + 16384;

            #pragma unroll
            for (int ks = 0; ks < 4; ks++) {
                issue_part(mL, nL, ktL, s_load, ks, vL);   // commit at ks==3
                if (ks < 3) {
                    load_frags(sa, sb, ks + 1, (ks + 1) & 1);
                } else {
                    CP_ASYNC_WAIT(1);                      // next chunk's stage landed
                    __syncthreads();                       // reads of stage s_cur done
                    load_frags(sa1, sb1, 0, 0);            // prefetch next chunk ks=0
                }
                compute(ks & 1);
            }
            s_cur = s_nf;
        }

        // ---- epilogue for tile (m0, n0): registers + gmem only ----
        #pragma unroll
        for (int mf = 0; mf < 4; mf++) {
            const int gr0 = m0 + warp_m + mf * 16 + (lane >> 2);
            const int gr1 = gr0 + 8;
            const float sa0 = g_ascale[gr0];
            const float sa1v = g_ascale[gr1];
            #pragma unroll
            for (int nf = 0; nf < 8; nf++) {
                const int gc = n0 + warp_n + nf * 8 + 2 * (lane & 3);
                const float sw0 = g_wscale[gc], sw1 = g_wscale[gc + 1];
                const float bb0 = bias[gc],     bb1 = bias[gc + 1];
                float2 v0, v1;
                v0.x = acc[mf][nf][0] * (sa0 * sw0) + bb0;
                v0.y = acc[mf][nf][1] * (sa0 * sw1) + bb1;
                v1.x = acc[mf][nf][2] * (sa1v * sw0) + bb0;
                v1.y = acc[mf][nf][3] * (sa1v * sw1) + bb1;
                *reinterpret_cast<float2*>(out + (size_t)gr0 * N + gc) = v0;
                *reinterpret_cast<float2*>(out + (size_t)gr1 * N + gc) = v1;
            }
        }

        if (!has_next) break;

        // advance to next tile; pipeline (loads + frag prefetch) already running
        m0 = m0n; n0 = n0n;
        tile_nx += gridDim.x;
        has_next = (tile_nx < ntiles);
        if (has_next) { m0n = (tile_nx / NT) << 7; n0n = (tile_nx % NT) << 7; }

        #pragma unroll
        for (int i = 0; i < 4; i++)
            #pragma unroll
            for (int j = 0; j < 8; j++)
                #pragma unroll
                for (int r = 0; r < 4; r++) acc[i][j][r] = 0.0f;
    }
}

// ======================= launch =======================

extern "C" void kernel_launch(void* const* d_in, const int* in_sizes, int n_in,
                              void* d_out, int out_size) {
    const float* x    = (const float*)d_in[0];
    const float* w    = (const float*)d_in[1];
    const float* bias = (const float*)d_in[2];
    float* out        = (float*)d_out;

    const int N = in_sizes[2];          // 4096
    const int K = in_sizes[1] / N;      // 4096
    const int M = in_sizes[0] / K;      // 8192

    cudaFuncSetAttribute(gemm_kernel,
                         cudaFuncAttributeMaxDynamicSharedMemorySize, GEMM_SMEM);

    quant_kernel<<<N + M, 256>>>(w, x, N, K);

    const int ntiles = (M / 128) * (N / 128);
    int grid = 296;                      // 2 CTAs x 148 SMs
    if (grid > ntiles) grid = ntiles;
    gemm_kernel<<<grid, 128, GEMM_SMEM>>>(out, bias, M, N, K);
}